// round 11
// baseline (speedup 1.0000x reference)
#include <cuda_runtime.h>
#include <stdint.h>
#include <math.h>

// ---------------------------------------------------------------------------
// RandomPhongShader: N=8, H=256, W=256, K=8, NB_SAMPLES=4
// SIGMA=0.1, GAMMA=0.1, ZNEAR=1, ZFAR=100, EPS=1e-10
//
// JAX threefry PRNG, partitionable mode:
//   random_bits(32)[i] = out0 ^ out1 of threefry(key, hi=0, lo=i)
//
// R11: rotate-on-FMA-pipe. rotl(x,r) = (x*2^r).lo | (x*2^r).hi via
// IMAD.WIDE.U32 (FMA pipe) instead of SHF (ALU pipe); the 2^r multipliers
// are RUNTIME params (uniform regs) so ptxas cannot strength-reduce back to
// shifts. (lo|hi)^x0 fuses into one LOP3. k2 hoisted to host (-64 LOP3/pix).
// Moves ~1280 ops/pixel ALU->FMA; decision bits identical ->
// rel_err canary 1.287565e-08.
// ---------------------------------------------------------------------------

#define NPIX (8 * 256 * 256)          // 524288 pixels
#define STRIDE_H 4194304u             // N*H*W*K     (per-sample stride, noise_h)
#define STRIDE_A 4718592u             // N*H*W*(K+1) (per-sample stride, noise_a)

struct RotP {   // 2^r for r in threefry-2x32 rotation schedule (runtime-opaque)
    uint32_t p13, p15, p26, p6, p17, p29, p16, p24;
};

// rotl via widening multiply: lo = x<<r, hi = x>>(32-r); OR+XOR fuse to LOP3.
#define TFROT(P) { x0 += x1;                                                  \
    unsigned long long pr = (unsigned long long)x1 * (P);                     \
    x1 = ((uint32_t)pr | (uint32_t)(pr >> 32)) ^ x0; }

// Full Threefry-2x32 with x0 = 0 (hi), x1 = ctr (lo); returns out0 ^ out1.
__device__ __forceinline__ uint32_t tf_xor(uint32_t k0, uint32_t k1, uint32_t k2,
                                           uint32_t ctr, const RotP rp)
{
    uint32_t x0 = k0;          // 0 + k0
    uint32_t x1 = ctr + k1;
    TFROT(rp.p13) TFROT(rp.p15) TFROT(rp.p26) TFROT(rp.p6)
    x0 += k1; x1 += k2 + 1u;
    TFROT(rp.p17) TFROT(rp.p29) TFROT(rp.p16) TFROT(rp.p24)
    x0 += k2; x1 += k0 + 2u;
    TFROT(rp.p13) TFROT(rp.p15) TFROT(rp.p26) TFROT(rp.p6)
    x0 += k0; x1 += k1 + 3u;
    TFROT(rp.p17) TFROT(rp.p29) TFROT(rp.p16) TFROT(rp.p24)
    x0 += k1; x1 += k2 + 4u;
    TFROT(rp.p13) TFROT(rp.p15) TFROT(rp.p26) TFROT(rp.p6)
    x0 += k2; x1 += k0 + 5u;
    return x0 ^ x1;
}

// Giles erf_inv (same coefficients as XLA), FMA form + MUFU log.
__device__ __forceinline__ float erfinv_fast(float x)
{
    float t = __fmaf_rn(-x, x, 1.0f);          // 1 - x*x
    float w = -__logf(t);                      // MUFU LG2 * ln2
    float p;
    if (w < 5.0f) {
        w = w - 2.5f;
        p = 2.81022636e-08f;
        p = __fmaf_rn(p, w, 3.43273939e-07f);
        p = __fmaf_rn(p, w, -3.5233877e-06f);
        p = __fmaf_rn(p, w, -4.39150654e-06f);
        p = __fmaf_rn(p, w, 0.00021858087f);
        p = __fmaf_rn(p, w, -0.00125372503f);
        p = __fmaf_rn(p, w, -0.00417768164f);
        p = __fmaf_rn(p, w, 0.246640727f);
        p = __fmaf_rn(p, w, 1.50140941f);
    } else {
        w = sqrtf(w) - 3.0f;
        p = -0.000200214257f;
        p = __fmaf_rn(p, w, 0.000100950558f);
        p = __fmaf_rn(p, w, 0.00134934322f);
        p = __fmaf_rn(p, w, -0.00367342844f);
        p = __fmaf_rn(p, w, 0.00573950773f);
        p = __fmaf_rn(p, w, -0.0076224613f);
        p = __fmaf_rn(p, w, 0.00943887047f);
        p = __fmaf_rn(p, w, 1.00167406f);
        p = __fmaf_rn(p, w, 2.83297682f);
    }
    return p * x;
}

// m = bits>>9 -> N(0,1); exact same fp sequence as the reference mapping.
__device__ __forceinline__ float m_to_normal(uint32_t m)
{
    const float LO    = __uint_as_float(0xBF7FFFFFu);  // nextafter(-1, 0)
    const float SQRT2 = __uint_as_float(0x3FB504F3u);  // float32(sqrt(2))
    float u = __fmaf_rn((float)m, 0x1.0p-22f, LO);     // exact prod, 1 rounding
    return SQRT2 * erfinv_fast(u);
}

// Rare exact heaviside fallback; out of line to keep the hot path small.
__device__ __noinline__ int heaviside_exact(float x, uint32_t m)
{
    return (__fadd_rn(x, __fmul_rn(0.1f, m_to_normal(m))) >= 0.0f) ? 1 : 0;
}

// Abramowitz-Stegun 7.1.26 erf, |abs err| <= ~1.5e-7 (plus expf/div ~1e-7).
__device__ __forceinline__ float erf_approx(float z)
{
    float az = fminf(fabsf(z), 4.0f);      // erf(4) = 1 - 1.5e-8, saturate
    float t  = __fdividef(1.0f, __fmaf_rn(0.3275911f, az, 1.0f));
    float y  = 1.061405429f;
    y = __fmaf_rn(y, t, -1.453152027f);
    y = __fmaf_rn(y, t,  1.421413741f);
    y = __fmaf_rn(y, t, -0.284496736f);
    y = __fmaf_rn(y, t,  0.254829592f);
    y = y * t;
    float e = __expf(-az * az);
    float r = __fmaf_rn(-y, e, 1.0f);
    return (z < 0.0f) ? -r : r;
}

__global__ void __launch_bounds__(256, 8)
rps_kernel(const float* __restrict__ colors,   // (N,H,W,K,3)
           const float* __restrict__ dists,    // (N,H,W,K)
           const float* __restrict__ zbuf,     // (N,H,W,K)
           const int*   __restrict__ p2f,      // (N,H,W,K)
           const float* __restrict__ bg,       // (3,)
           float*       __restrict__ out,      // (N,H,W,4)
           uint32_t kh0, uint32_t kh1, uint32_t kh2,
           uint32_t ka0, uint32_t ka1, uint32_t ka2,
           float l0, float l1, float l2, float l3, float l4,
           RotP rp)
{
    __shared__ float2 zl_s[8 * 256];   // (zinv, logp) per face per thread
    __shared__ float  lut_s[5];

    unsigned tid = threadIdx.x;
    unsigned pix = blockIdx.x * 256u + tid;   // grid is exactly NPIX/256

    if (tid == 0) {
        lut_s[0] = l0; lut_s[1] = l1; lut_s[2] = l2; lut_s[3] = l3; lut_s[4] = l4;
    }
    __syncthreads();

    const float* dp = dists + (size_t)pix * 8;
    const float* zp = zbuf  + (size_t)pix * 8;
    const int*   fp = p2f   + (size_t)pix * 8;

    // ---- phase 1: heaviside via integer threshold; alpha; (zinv,logp) ------
    float alpha = 1.0f;
    float zmax  = -1e30f;
    uint32_t bh = pix * 8u;

#pragma unroll 1
    for (int k = 0; k < 8; ++k) {
        float d = __ldg(dp + k);
        float z = __ldg(zp + k);
        int   f = __ldg(fp + k);
        bool msk = (f >= 0);
        float mask = msk ? 1.0f : 0.0f;
        uint32_t b = bh + (uint32_t)k;
        float x = -d;

        // threshold on m = bits>>9: decision is (m >= m*), |m* - mth| << 64
        float uth = erf_approx(d * 7.0710678f);                 // erf(10d/sqrt2)
        // (uth - LO)*2^22 ; -LO*2^22 = (1-2^-24)*2^22 = 4194303.75 exactly
        int mth = __float2int_rn(__fmaf_rn(uth, 4194304.0f, 4194303.75f));
        int mhi = mth + 64;
        int mlo = mth - 64;

        int cnt = 0;
#pragma unroll
        for (int s = 0; s < 4; ++s) {
            uint32_t bits = tf_xor(kh0, kh1, kh2, b + (uint32_t)s * STRIDE_H, rp);
            int m = (int)(bits >> 9);
            if (m >= mhi) {
                cnt++;
            } else if (m > mlo) {   // rare exact fallback (~3e-5 per sample)
                cnt += heaviside_exact(x, (uint32_t)m);
            }
        }

        int idx = msk ? cnt : 0;
        float prob = __fmul_rn((float)cnt * 0.25f, mask);   // exact
        alpha = __fmul_rn(alpha, 1.0f - prob);              // exact product
        float zinvk = __fmul_rn(__fdiv_rn(__fsub_rn(100.0f, z), 99.0f), mask);
        zmax = fmaxf(zmax, zinvk);
        float2 zl; zl.x = zinvk; zl.y = lut_s[idx];
        zl_s[k * 256 + tid] = zl;
    }
    zmax = fmaxf(zmax, 1e-10f);

    // ---- phase 2: random argmax, faces j=0..7, 4 samples, first-max-wins ---
    float b0 = -1e30f, b1 = -1e30f, b2 = -1e30f, b3 = -1e30f;
    int   i0 = 0, i1 = 0, i2 = 0, i3 = 0;
    uint32_t ba = pix * 9u;

#pragma unroll 2
    for (int j = 0; j < 8; ++j) {
        float2 zl = zl_s[j * 256 + tid];
        float zmj = __fadd_rn(zl.y, __fdiv_rn(__fsub_rn(zl.x, zmax), 0.1f));

        uint32_t c = ba + (uint32_t)j;
        float s0 = __fadd_rn(zmj, __fmul_rn(0.1f, m_to_normal(tf_xor(ka0, ka1, ka2, c, rp) >> 9)));
        float s1 = __fadd_rn(zmj, __fmul_rn(0.1f, m_to_normal(tf_xor(ka0, ka1, ka2, c + STRIDE_A, rp) >> 9)));
        float s2 = __fadd_rn(zmj, __fmul_rn(0.1f, m_to_normal(tf_xor(ka0, ka1, ka2, c + 2u * STRIDE_A, rp) >> 9)));
        float s3 = __fadd_rn(zmj, __fmul_rn(0.1f, m_to_normal(tf_xor(ka0, ka1, ka2, c + 3u * STRIDE_A, rp) >> 9)));
        if (s0 > b0) { b0 = s0; i0 = j; }
        if (s1 > b1) { b1 = s1; i1 = j; }
        if (s2 > b2) { b2 = s2; i2 = j; }
        if (s3 > b3) { b3 = s3; i3 = j; }
    }
    // Background (j=8): max |0.1*noise| = 0.543 < 0.6; if zm8 can't reach the
    // weakest running best it can never win any sample -> skip (~never taken).
    {
        float zm8 = __fdiv_rn(__fsub_rn(1e-10f, zmax), 0.1f);
        float bmin = fminf(fminf(b0, b1), fminf(b2, b3));
        if (zm8 > bmin - 0.6f) {
            uint32_t c = ba + 8u;
            float s0 = __fadd_rn(zm8, __fmul_rn(0.1f, m_to_normal(tf_xor(ka0, ka1, ka2, c, rp) >> 9)));
            float s1 = __fadd_rn(zm8, __fmul_rn(0.1f, m_to_normal(tf_xor(ka0, ka1, ka2, c + STRIDE_A, rp) >> 9)));
            float s2 = __fadd_rn(zm8, __fmul_rn(0.1f, m_to_normal(tf_xor(ka0, ka1, ka2, c + 2u * STRIDE_A, rp) >> 9)));
            float s3 = __fadd_rn(zm8, __fmul_rn(0.1f, m_to_normal(tf_xor(ka0, ka1, ka2, c + 3u * STRIDE_A, rp) >> 9)));
            if (s0 > b0) { i0 = 8; }
            if (s1 > b1) { i1 = 8; }
            if (s2 > b2) { i2 = 8; }
            if (s3 > b3) { i3 = 8; }
        }
    }

    // ---- phase 3: weighted colors (reference summation order k=0..7) ------
    const float* cp = colors + (size_t)pix * 24;
    float r = 0.f, g = 0.f, bl = 0.f;
#pragma unroll 1
    for (int k = 0; k < 8; ++k) {
        int cnt = (i0 == k) + (i1 == k) + (i2 == k) + (i3 == k);
        float wk = __fmul_rn((float)cnt, 0.25f);
        r  = __fadd_rn(r,  __fmul_rn(wk, __ldg(cp + 3 * k + 0)));
        g  = __fadd_rn(g,  __fmul_rn(wk, __ldg(cp + 3 * k + 1)));
        bl = __fadd_rn(bl, __fmul_rn(wk, __ldg(cp + 3 * k + 2)));
    }
    int cntb = (i0 == 8) + (i1 == 8) + (i2 == 8) + (i3 == 8);
    float wb = __fmul_rn((float)cntb, 0.25f);

    float4 o;
    o.x = __fadd_rn(r,  __fmul_rn(wb, bg[0]));
    o.y = __fadd_rn(g,  __fmul_rn(wb, bg[1]));
    o.z = __fadd_rn(bl, __fmul_rn(wb, bg[2]));
    o.w = 1.0f - alpha;
    *(float4*)(out + (size_t)pix * 4) = o;
}

// ---------------------------------------------------------------------------
// Host-side threefry for key derivation (full 2-word output).
// ---------------------------------------------------------------------------
static void threefry_host(uint32_t k0, uint32_t k1, uint32_t x0, uint32_t x1,
                          uint32_t* o0, uint32_t* o1)
{
    uint32_t k2 = k0 ^ k1 ^ 0x1BD11BDAu;
    x0 += k0; x1 += k1;
#define R(r) { x0 += x1; x1 = (x1 << (r)) | (x1 >> (32 - (r))); x1 ^= x0; }
    R(13) R(15) R(26) R(6)
    x0 += k1; x1 += k2 + 1u;
    R(17) R(29) R(16) R(24)
    x0 += k2; x1 += k0 + 2u;
    R(13) R(15) R(26) R(6)
    x0 += k0; x1 += k1 + 3u;
    R(17) R(29) R(16) R(24)
    x0 += k1; x1 += k2 + 4u;
    R(13) R(15) R(26) R(6)
    x0 += k2; x1 += k0 + 5u;
#undef R
    *o0 = x0; *o1 = x1;
}

extern "C" void kernel_launch(void* const* d_in, const int* in_sizes, int n_in,
                              void* d_out, int out_size)
{
    const float* colors = (const float*)d_in[0];
    const float* dists  = (const float*)d_in[1];
    const float* zbuf   = (const float*)d_in[2];
    const int*   p2f    = (const int*)  d_in[3];
    const float* bg     = (const float*)d_in[4];
    float*       out    = (float*)d_out;

    // jax.random.key(1) -> raw key (0, 1); partitionable split.
    uint32_t kh0, kh1, ka0, ka1;
    threefry_host(0u, 1u, 0u, 0u, &kh0, &kh1);   // kh = keys[0]
    threefry_host(0u, 1u, 0u, 1u, &ka0, &ka1);   // ka = keys[1]
    uint32_t kh2 = kh0 ^ kh1 ^ 0x1BD11BDAu;
    uint32_t ka2 = ka0 ^ ka1 ^ 0x1BD11BDAu;

    // log(EPS + prob) LUT, prob in {0, 0.25, 0.5, 0.75, 1.0}.
    float l0 = (float)log((double)1e-10f);
    float l1 = (float)log((double)(1e-10f + 0.25f));
    float l2 = (float)log((double)(1e-10f + 0.5f));
    float l3 = (float)log((double)(1e-10f + 0.75f));
    float l4 = (float)log((double)(1e-10f + 1.0f));

    RotP rp;
    rp.p13 = 1u << 13; rp.p15 = 1u << 15; rp.p26 = 1u << 26; rp.p6  = 1u << 6;
    rp.p17 = 1u << 17; rp.p29 = 1u << 29; rp.p16 = 1u << 16; rp.p24 = 1u << 24;

    dim3 grid(NPIX / 256);
    rps_kernel<<<grid, 256>>>(colors, dists, zbuf, p2f, bg, out,
                              kh0, kh1, kh2, ka0, ka1, ka2,
                              l0, l1, l2, l3, l4, rp);
}

// round 12
// speedup vs baseline: 1.3301x; 1.3301x over previous
#include <cuda_runtime.h>
#include <stdint.h>
#include <math.h>

// ---------------------------------------------------------------------------
// RandomPhongShader: N=8, H=256, W=256, K=8, NB_SAMPLES=4
// SIGMA=0.1, GAMMA=0.1, ZNEAR=1, ZFAR=100, EPS=1e-10
//
// JAX threefry PRNG, partitionable mode:
//   random_bits(32)[i] = out0 ^ out1 of threefry(key, hi=0, lo=i)
//
// R12: warp-compacted heaviside. 0.1*noise spans [-0.54312, +0.5332] exactly,
// so |d| >= 0.55 decides all 4 samples without bits (58% of faces). Needy
// lanes (ballot, E~13/warp) have their 4n evals spread across all 32 lanes
// (__fns owner lookup + shfl of threshold), outcomes routed back via ballot
// (an owner's 4 bits share one word: 4*idx mod 32 <= 28). E[rounds]=2.07 ->
// heaviside threefry 32 -> ~16.6 calls/pixel. Needy path math identical ->
// rel_err canary 1.287565e-08.
// ---------------------------------------------------------------------------

#define NPIX (8 * 256 * 256)          // 524288 pixels
#define STRIDE_H 4194304u             // N*H*W*K     (per-sample stride, noise_h)
#define STRIDE_A 4718592u             // N*H*W*(K+1) (per-sample stride, noise_a)

// Full Threefry-2x32 with x0 = 0 (hi), x1 = ctr (lo); returns out0 ^ out1.
__device__ __forceinline__ uint32_t tf_xor(uint32_t k0, uint32_t k1, uint32_t ctr)
{
    uint32_t k2 = k0 ^ k1 ^ 0x1BD11BDAu;
    uint32_t x0 = k0;          // 0 + k0
    uint32_t x1 = ctr + k1;
#define TFR(r) { x0 += x1; x1 = __funnelshift_l(x1, x1, (r)); x1 ^= x0; }
    TFR(13) TFR(15) TFR(26) TFR(6)
    x0 += k1; x1 += k2 + 1u;
    TFR(17) TFR(29) TFR(16) TFR(24)
    x0 += k2; x1 += k0 + 2u;
    TFR(13) TFR(15) TFR(26) TFR(6)
    x0 += k0; x1 += k1 + 3u;
    TFR(17) TFR(29) TFR(16) TFR(24)
    x0 += k1; x1 += k2 + 4u;
    TFR(13) TFR(15) TFR(26) TFR(6)
    x0 += k2; x1 += k0 + 5u;
#undef TFR
    return x0 ^ x1;
}

// Giles erf_inv (same coefficients as XLA), FMA form + MUFU log.
__device__ __forceinline__ float erfinv_fast(float x)
{
    float t = __fmaf_rn(-x, x, 1.0f);          // 1 - x*x
    float w = -__logf(t);                      // MUFU LG2 * ln2
    float p;
    if (w < 5.0f) {
        w = w - 2.5f;
        p = 2.81022636e-08f;
        p = __fmaf_rn(p, w, 3.43273939e-07f);
        p = __fmaf_rn(p, w, -3.5233877e-06f);
        p = __fmaf_rn(p, w, -4.39150654e-06f);
        p = __fmaf_rn(p, w, 0.00021858087f);
        p = __fmaf_rn(p, w, -0.00125372503f);
        p = __fmaf_rn(p, w, -0.00417768164f);
        p = __fmaf_rn(p, w, 0.246640727f);
        p = __fmaf_rn(p, w, 1.50140941f);
    } else {
        w = sqrtf(w) - 3.0f;
        p = -0.000200214257f;
        p = __fmaf_rn(p, w, 0.000100950558f);
        p = __fmaf_rn(p, w, 0.00134934322f);
        p = __fmaf_rn(p, w, -0.00367342844f);
        p = __fmaf_rn(p, w, 0.00573950773f);
        p = __fmaf_rn(p, w, -0.0076224613f);
        p = __fmaf_rn(p, w, 0.00943887047f);
        p = __fmaf_rn(p, w, 1.00167406f);
        p = __fmaf_rn(p, w, 2.83297682f);
    }
    return p * x;
}

// m = bits>>9 -> N(0,1); exact same fp sequence as the reference mapping.
__device__ __forceinline__ float m_to_normal(uint32_t m)
{
    const float LO    = __uint_as_float(0xBF7FFFFFu);  // nextafter(-1, 0)
    const float SQRT2 = __uint_as_float(0x3FB504F3u);  // float32(sqrt(2))
    float u = __fmaf_rn((float)m, 0x1.0p-22f, LO);     // exact prod, 1 rounding
    return SQRT2 * erfinv_fast(u);
}

// Rare exact heaviside fallback; out of line to keep the hot path small.
__device__ __noinline__ int heaviside_exact(float x, uint32_t m)
{
    return (__fadd_rn(x, __fmul_rn(0.1f, m_to_normal(m))) >= 0.0f) ? 1 : 0;
}

// Abramowitz-Stegun 7.1.26 erf, |abs err| <= ~1.5e-7 (plus expf/div ~1e-7).
__device__ __forceinline__ float erf_approx(float z)
{
    float az = fminf(fabsf(z), 4.0f);      // erf(4) = 1 - 1.5e-8, saturate
    float t  = __fdividef(1.0f, __fmaf_rn(0.3275911f, az, 1.0f));
    float y  = 1.061405429f;
    y = __fmaf_rn(y, t, -1.453152027f);
    y = __fmaf_rn(y, t,  1.421413741f);
    y = __fmaf_rn(y, t, -0.284496736f);
    y = __fmaf_rn(y, t,  0.254829592f);
    y = y * t;
    float e = __expf(-az * az);
    float r = __fmaf_rn(-y, e, 1.0f);
    return (z < 0.0f) ? -r : r;
}

__global__ void __launch_bounds__(256, 6)
rps_kernel(const float* __restrict__ colors,   // (N,H,W,K,3)
           const float* __restrict__ dists,    // (N,H,W,K)
           const float* __restrict__ zbuf,     // (N,H,W,K)
           const int*   __restrict__ p2f,      // (N,H,W,K)
           const float* __restrict__ bg,       // (3,)
           float*       __restrict__ out,      // (N,H,W,4)
           uint32_t kh0, uint32_t kh1, uint32_t ka0, uint32_t ka1,
           float l0, float l1, float l2, float l3, float l4)
{
    __shared__ float2 zl_s[8 * 256];   // (zinv, logp) per face per thread
    __shared__ float  lut_s[5];

    unsigned tid  = threadIdx.x;
    unsigned lane = tid & 31u;
    unsigned pix  = blockIdx.x * 256u + tid;   // grid is exactly NPIX/256
    uint32_t warpbase8 = (pix - lane) * 8u;    // lane0's pixel * 8

    if (tid == 0) {
        lut_s[0] = l0; lut_s[1] = l1; lut_s[2] = l2; lut_s[3] = l3; lut_s[4] = l4;
    }
    __syncthreads();

    const float* dp = dists + (size_t)pix * 8;
    const float* zp = zbuf  + (size_t)pix * 8;
    const int*   fp = p2f   + (size_t)pix * 8;

    // ---- phase 1: heaviside, warp-compacted over undecided lanes -----------
    float alpha = 1.0f;
    float zmax  = -1e30f;

#pragma unroll 1
    for (int k = 0; k < 8; ++k) {
        float d = __ldg(dp + k);
        float z = __ldg(zp + k);
        int   f = __ldg(fp + k);
        bool msk = (f >= 0);
        float mask = msk ? 1.0f : 0.0f;
        float x = -d;

        // |0.1*noise| extreme values: [-0.54312, +0.5332]; outside +-0.55 the
        // decision is the same for every m -> no bits needed. (Masked lanes
        // never need cnt: prob and idx are forced to 0.)
        bool need = msk && (fabsf(d) < 0.55f);
        unsigned nmask = __ballot_sync(0xFFFFFFFFu, need);
        int total = 4 * __popc(nmask);

        // threshold on m = bits>>9 (only read for needy lanes, via shfl)
        float uth = erf_approx(d * 7.0710678f);                 // erf(10d/sqrt2)
        int mth = __float2int_rn(__fmaf_rn(uth, 4194304.0f, 4194303.75f));
        int mhi = mth + 64;    // mlo = mhi - 128

        uint32_t bal0 = 0, bal1 = 0, bal2 = 0, bal3 = 0;
#pragma unroll
        for (int r = 0; r < 4; ++r) {
            if (r * 32 >= total) break;          // warp-uniform
            int e = r * 32 + (int)lane;
            bool active = e < total;
            int oidx = e >> 2;                    // which needy lane (by rank)
            int s    = e & 3;                     // which sample
            unsigned owner = __fns(nmask, 0, oidx + 1);
            int own = active ? (int)owner : 0;
            int   mhi_o = __shfl_sync(0xFFFFFFFFu, mhi, own);
            float x_o   = __shfl_sync(0xFFFFFFFFu, x,   own);
            uint32_t ctr = warpbase8 + (uint32_t)own * 8u + (uint32_t)k
                         + (uint32_t)s * STRIDE_H;
            uint32_t bits = tf_xor(kh0, kh1, ctr);
            int m = (int)(bits >> 9);
            bool win = false;
            if (active) {
                if (m >= mhi_o)          win = true;
                else if (m > mhi_o - 128) win = (heaviside_exact(x_o, (uint32_t)m) != 0);
            }
            uint32_t bal = __ballot_sync(0xFFFFFFFFu, win);
            if      (r == 0) bal0 = bal;
            else if (r == 1) bal1 = bal;
            else if (r == 2) bal2 = bal;
            else             bal3 = bal;
        }

        int cnt;
        if (need) {
            int base4 = 4 * __popc(nmask & ((1u << lane) - 1u));  // 4*rank
            uint32_t w = (base4 & 64) ? ((base4 & 32) ? bal3 : bal2)
                                      : ((base4 & 32) ? bal1 : bal0);
            cnt = __popc((w >> (base4 & 31)) & 0xFu);
        } else {
            cnt = (d <= -0.55f) ? 4 : 0;   // masked lanes: value irrelevant
        }

        int idx = msk ? cnt : 0;
        float prob = __fmul_rn((float)cnt * 0.25f, mask);   // exact
        alpha = __fmul_rn(alpha, 1.0f - prob);              // exact product
        float zinvk = __fmul_rn(__fdiv_rn(__fsub_rn(100.0f, z), 99.0f), mask);
        zmax = fmaxf(zmax, zinvk);
        float2 zl; zl.x = zinvk; zl.y = lut_s[idx];
        zl_s[k * 256 + tid] = zl;
    }
    zmax = fmaxf(zmax, 1e-10f);

    // ---- phase 2: random argmax, faces j=0..7, 4 samples, first-max-wins ---
    float b0 = -1e30f, b1 = -1e30f, b2 = -1e30f, b3 = -1e30f;
    int   i0 = 0, i1 = 0, i2 = 0, i3 = 0;
    uint32_t ba = pix * 9u;

#pragma unroll 2
    for (int j = 0; j < 8; ++j) {
        float2 zl = zl_s[j * 256 + tid];
        float zmj = __fadd_rn(zl.y, __fdiv_rn(__fsub_rn(zl.x, zmax), 0.1f));

        uint32_t c = ba + (uint32_t)j;
        float s0 = __fadd_rn(zmj, __fmul_rn(0.1f, m_to_normal(tf_xor(ka0, ka1, c) >> 9)));
        float s1 = __fadd_rn(zmj, __fmul_rn(0.1f, m_to_normal(tf_xor(ka0, ka1, c + STRIDE_A) >> 9)));
        float s2 = __fadd_rn(zmj, __fmul_rn(0.1f, m_to_normal(tf_xor(ka0, ka1, c + 2u * STRIDE_A) >> 9)));
        float s3 = __fadd_rn(zmj, __fmul_rn(0.1f, m_to_normal(tf_xor(ka0, ka1, c + 3u * STRIDE_A) >> 9)));
        if (s0 > b0) { b0 = s0; i0 = j; }
        if (s1 > b1) { b1 = s1; i1 = j; }
        if (s2 > b2) { b2 = s2; i2 = j; }
        if (s3 > b3) { b3 = s3; i3 = j; }
    }
    // Background (j=8): max |0.1*noise| = 0.543 < 0.6; if zm8 can't reach the
    // weakest running best it can never win any sample -> skip (~never taken).
    {
        float zm8 = __fdiv_rn(__fsub_rn(1e-10f, zmax), 0.1f);
        float bmin = fminf(fminf(b0, b1), fminf(b2, b3));
        if (zm8 > bmin - 0.6f) {
            uint32_t c = ba + 8u;
            float s0 = __fadd_rn(zm8, __fmul_rn(0.1f, m_to_normal(tf_xor(ka0, ka1, c) >> 9)));
            float s1 = __fadd_rn(zm8, __fmul_rn(0.1f, m_to_normal(tf_xor(ka0, ka1, c + STRIDE_A) >> 9)));
            float s2 = __fadd_rn(zm8, __fmul_rn(0.1f, m_to_normal(tf_xor(ka0, ka1, c + 2u * STRIDE_A) >> 9)));
            float s3 = __fadd_rn(zm8, __fmul_rn(0.1f, m_to_normal(tf_xor(ka0, ka1, c + 3u * STRIDE_A) >> 9)));
            if (s0 > b0) { i0 = 8; }
            if (s1 > b1) { i1 = 8; }
            if (s2 > b2) { i2 = 8; }
            if (s3 > b3) { i3 = 8; }
        }
    }

    // ---- phase 3: weighted colors (reference summation order k=0..7) ------
    const float* cp = colors + (size_t)pix * 24;
    float r = 0.f, g = 0.f, bl = 0.f;
#pragma unroll 1
    for (int k = 0; k < 8; ++k) {
        int cnt = (i0 == k) + (i1 == k) + (i2 == k) + (i3 == k);
        float wk = __fmul_rn((float)cnt, 0.25f);
        r  = __fadd_rn(r,  __fmul_rn(wk, __ldg(cp + 3 * k + 0)));
        g  = __fadd_rn(g,  __fmul_rn(wk, __ldg(cp + 3 * k + 1)));
        bl = __fadd_rn(bl, __fmul_rn(wk, __ldg(cp + 3 * k + 2)));
    }
    int cntb = (i0 == 8) + (i1 == 8) + (i2 == 8) + (i3 == 8);
    float wb = __fmul_rn((float)cntb, 0.25f);

    float4 o;
    o.x = __fadd_rn(r,  __fmul_rn(wb, bg[0]));
    o.y = __fadd_rn(g,  __fmul_rn(wb, bg[1]));
    o.z = __fadd_rn(bl, __fmul_rn(wb, bg[2]));
    o.w = 1.0f - alpha;
    *(float4*)(out + (size_t)pix * 4) = o;
}

// ---------------------------------------------------------------------------
// Host-side threefry for key derivation (full 2-word output).
// ---------------------------------------------------------------------------
static void threefry_host(uint32_t k0, uint32_t k1, uint32_t x0, uint32_t x1,
                          uint32_t* o0, uint32_t* o1)
{
    uint32_t k2 = k0 ^ k1 ^ 0x1BD11BDAu;
    x0 += k0; x1 += k1;
#define R(r) { x0 += x1; x1 = (x1 << (r)) | (x1 >> (32 - (r))); x1 ^= x0; }
    R(13) R(15) R(26) R(6)
    x0 += k1; x1 += k2 + 1u;
    R(17) R(29) R(16) R(24)
    x0 += k2; x1 += k0 + 2u;
    R(13) R(15) R(26) R(6)
    x0 += k0; x1 += k1 + 3u;
    R(17) R(29) R(16) R(24)
    x0 += k1; x1 += k2 + 4u;
    R(13) R(15) R(26) R(6)
    x0 += k2; x1 += k0 + 5u;
#undef R
    *o0 = x0; *o1 = x1;
}

extern "C" void kernel_launch(void* const* d_in, const int* in_sizes, int n_in,
                              void* d_out, int out_size)
{
    const float* colors = (const float*)d_in[0];
    const float* dists  = (const float*)d_in[1];
    const float* zbuf   = (const float*)d_in[2];
    const int*   p2f    = (const int*)  d_in[3];
    const float* bg     = (const float*)d_in[4];
    float*       out    = (float*)d_out;

    // jax.random.key(1) -> raw key (0, 1); partitionable split.
    uint32_t kh0, kh1, ka0, ka1;
    threefry_host(0u, 1u, 0u, 0u, &kh0, &kh1);   // kh = keys[0]
    threefry_host(0u, 1u, 0u, 1u, &ka0, &ka1);   // ka = keys[1]

    // log(EPS + prob) LUT, prob in {0, 0.25, 0.5, 0.75, 1.0}.
    float l0 = (float)log((double)1e-10f);
    float l1 = (float)log((double)(1e-10f + 0.25f));
    float l2 = (float)log((double)(1e-10f + 0.5f));
    float l3 = (float)log((double)(1e-10f + 0.75f));
    float l4 = (float)log((double)(1e-10f + 1.0f));

    dim3 grid(NPIX / 256);
    rps_kernel<<<grid, 256>>>(colors, dists, zbuf, p2f, bg, out,
                              kh0, kh1, ka0, ka1, l0, l1, l2, l3, l4);
}